// round 16
// baseline (speedup 1.0000x reference)
#include <cuda_runtime.h>
#include <cuda_fp16.h>
#include <cstdint>
#include <math.h>

typedef __half hf;

// Problem constants
#define BQ   4
#define NQ   2048
#define DM   2048
#define KVH_ 4
#define HD_  128
#define KVD_ 512
#define GRP_ 4

// ---------------------------------------------------------------------------
// Device scratch
// ---------------------------------------------------------------------------
__device__ float g_bq_eff[KVD_];

__device__ hf g_qh[(size_t)BQ * NQ * DM];
__device__ hf g_kh[(size_t)BQ * NQ * DM];
__device__ hf g_vh[(size_t)BQ * NQ * DM];

__device__ hf g_WqTh[DM * KVD_];
__device__ hf g_WkTh[DM * KVD_];
__device__ hf g_WvTh[DM * KVD_];
__device__ hf g_WoTh[DM * KVD_];

__device__ hf g_VtH[(size_t)BQ * KVD_ * NQ];

__device__ hf g_Qeh[(size_t)BQ * NQ * KVD_], g_Qel[(size_t)BQ * NQ * KVD_];
__device__ hf g_Kph[(size_t)BQ * NQ * KVD_];
__device__ hf g_Xh [(size_t)BQ * NQ * KVD_];

__device__ hf g_Eh[(size_t)BQ * KVH_ * NQ * NQ];
__device__ float g_partial[16 * 16 * 2048];   // [z][xtile][row]
__device__ float g_invsum[16 * 2048];         // [z][row]
__device__ float g_attn_fb[(size_t)BQ * KVH_ * NQ * NQ];

// ---------------------------------------------------------------------------
// Helpers
// ---------------------------------------------------------------------------
__device__ __forceinline__ uint32_t smem_u32(const void* p) {
    uint32_t a;
    asm("{ .reg .u64 t; cvta.to.shared.u64 t, %1; cvt.u32.u64 %0, t; }" : "=r"(a) : "l"(p));
    return a;
}
__device__ __forceinline__ uint32_t swz(uint32_t row, uint32_t kb) {
    return row * 128u + (kb ^ ((row & 7u) << 4));
}
__device__ __forceinline__ void cp_async16(uint32_t dst, const void* src) {
    asm volatile("cp.async.cg.shared.global [%0], [%1], 16;" :: "r"(dst), "l"(src));
}
__device__ __forceinline__ void cp_commit() {
    asm volatile("cp.async.commit_group;" ::: "memory");
}
__device__ __forceinline__ void cp_wait1() {
    asm volatile("cp.async.wait_group 1;" ::: "memory");
}
__device__ __forceinline__ void cp_wait0() {
    asm volatile("cp.async.wait_group 0;" ::: "memory");
}
__device__ __forceinline__ void ldsm_x4(uint32_t& r0, uint32_t& r1, uint32_t& r2,
                                        uint32_t& r3, uint32_t addr) {
    asm volatile("ldmatrix.sync.aligned.m8n8.x4.shared.b16 {%0,%1,%2,%3}, [%4];"
        : "=r"(r0), "=r"(r1), "=r"(r2), "=r"(r3) : "r"(addr));
}
__device__ __forceinline__ void mma_fp16(float* c, const uint32_t* a, const uint32_t* b) {
    asm volatile(
        "mma.sync.aligned.m16n8k16.row.col.f32.f16.f16.f32 "
        "{%0,%1,%2,%3}, {%4,%5,%6,%7}, {%8,%9}, {%0,%1,%2,%3};"
        : "+f"(c[0]), "+f"(c[1]), "+f"(c[2]), "+f"(c[3])
        : "r"(a[0]), "r"(a[1]), "r"(a[2]), "r"(a[3]), "r"(b[0]), "r"(b[1]));
}
__device__ __forceinline__ void split2(float v0, float v1, __half2& h, __half2& l) {
    hf h0 = __float2half_rn(v0), h1 = __float2half_rn(v1);
    h = __halves2half2(h0, h1);
    l = __halves2half2(__float2half_rn(v0 - __half2float(h0)),
                       __float2half_rn(v1 - __half2float(h1)));
}

#define STAGE_BYTES 49152
#define SMEM_DYN (2 * STAGE_BYTES + 1024)

// ---------------------------------------------------------------------------
// GEMM mainloop core (round-10/14 proven form). MODE: 0 = 1-pass {A,Bh};
// 2 = 3-pass (phase A {Ah,Al,Bh}: Ah*Bh+Al*Bh; phase B {Ah,Bl}: Ah*Bl);
// 3 = 2-pass = MODE 2 phase A ONLY (NC=KC, Bl unused).
// REUSEA valid when KC<=2 (MODE 2 only). Ends with trailing __syncthreads().
// ---------------------------------------------------------------------------
template <int MODE, bool REUSEA>
__device__ __forceinline__ void gemm_core(
    const hf* __restrict__ Ah, const hf* __restrict__ Al,
    const hf* __restrict__ Bh, const hf* __restrict__ Bl,
    int K, int lda, int ldb, int cRow, int cCol,
    uint32_t sbase, int t, float acc[2][8][4])
{
    const int wid = t >> 5;
    const int lane = t & 31;
    const int wm = wid & 3;
    const int wn = wid >> 2;

    const int KC = K >> 6;
    const int NC = (MODE == 2) ? 2 * KC : KC;

    auto loadOp = [&](uint32_t dst, const hf* P, int ld, int base, int k0) {
        #pragma unroll
        for (int i = 0; i < 4; ++i) {
            int id = t + i * 256;
            int row = id >> 3, kc = id & 7;
            cp_async16(dst + swz(row, kc * 16),
                       P + (long long)(base + row) * ld + k0 + kc * 8);
        }
    };

    auto load_tile = [&](int c, int slot) {
        const uint32_t st = sbase + slot * STAGE_BYTES;
        if (MODE == 2 || MODE == 3) {
            const bool phA = (MODE == 3) || (c < KC);
            const int k0 = (phA ? c : c - KC) << 6;
            if (phA || !REUSEA) loadOp(st, Ah, lda, cRow, k0);
            if (phA) loadOp(st + 16384, Al, lda, cRow, k0);
            loadOp(st + 32768, phA ? Bh : Bl, ldb, cCol, k0);
        } else {
            const int k0 = c << 6;
            loadOp(st, Ah, lda, cRow, k0);
            loadOp(st + 16384, Bh, ldb, cCol, k0);
        }
    };

    const uint32_t a_row0 = wm * 32 + (lane & 15);
    const uint32_t a_kb   = (lane >> 4) * 16;
    const uint32_t b_row0 = wn * 64 + (lane & 7) + ((lane >> 4) << 3);
    const uint32_t b_kb   = ((lane >> 3) & 1) * 16;

    load_tile(0, 0); cp_commit();

    for (int c = 0; c < NC; ++c) {
        if (c + 1 < NC) { load_tile(c + 1, (c + 1) & 1); cp_commit(); cp_wait1(); }
        else            { cp_wait0(); }
        __syncthreads();

        const uint32_t st = sbase + (c & 1) * STAGE_BYTES;

        #pragma unroll
        for (int ks = 0; ks < 4; ++ks) {
            uint32_t afr[2][4];
            #pragma unroll
            for (int i = 0; i < 2; ++i)
                ldsm_x4(afr[i][0], afr[i][1], afr[i][2], afr[i][3],
                        st + swz(a_row0 + i * 16, ks * 32 + a_kb));

            if (MODE == 2 || MODE == 3) {
                uint32_t bfr[8][2];
                #pragma unroll
                for (int j2 = 0; j2 < 4; ++j2)
                    ldsm_x4(bfr[j2*2][0], bfr[j2*2][1], bfr[j2*2+1][0], bfr[j2*2+1][1],
                            st + 32768 + swz(b_row0 + j2 * 16, ks * 32 + b_kb));
                #pragma unroll
                for (int i = 0; i < 2; ++i)
                    #pragma unroll
                    for (int j = 0; j < 8; ++j)
                        mma_fp16(acc[i][j], afr[i], bfr[j]);
                if ((MODE == 3) || (c < KC)) {
                    uint32_t afr2[2][4];
                    #pragma unroll
                    for (int i = 0; i < 2; ++i)
                        ldsm_x4(afr2[i][0], afr2[i][1], afr2[i][2], afr2[i][3],
                                st + 16384 + swz(a_row0 + i * 16, ks * 32 + a_kb));
                    #pragma unroll
                    for (int i = 0; i < 2; ++i)
                        #pragma unroll
                        for (int j = 0; j < 8; ++j)
                            mma_fp16(acc[i][j], afr2[i], bfr[j]);
                }
            } else {
                uint32_t bfr[8][2];
                #pragma unroll
                for (int j2 = 0; j2 < 4; ++j2)
                    ldsm_x4(bfr[j2*2][0], bfr[j2*2][1], bfr[j2*2+1][0], bfr[j2*2+1][1],
                            st + 16384 + swz(b_row0 + j2 * 16, ks * 32 + b_kb));
                #pragma unroll
                for (int i = 0; i < 2; ++i)
                    #pragma unroll
                    for (int j = 0; j < 8; ++j)
                        mma_fp16(acc[i][j], afr[i], bfr[j]);
            }
        }
        __syncthreads();
    }
}

// ---------------------------------------------------------------------------
// Epilogue. EPI: 0 fp32+bias | 1 hi/lo fp16+bias | 2 exp->fp16 + partials
//               4 single fp16 + bias
// ---------------------------------------------------------------------------
template <int EPI>
__device__ __forceinline__ void epilogue(
    float acc[2][8][4], float* Cf, hf* Ch, hf* Cl,
    const float* bias, float* partial,
    int ldc, int cRow, int cCol, int z, int bx, int t, float scale)
{
    const int wid = t >> 5, lane = t & 31;
    const int wm = wid & 3, wn = wid >> 2;
    #pragma unroll
    for (int i = 0; i < 2; ++i) {
        #pragma unroll
        for (int half = 0; half < 2; ++half) {
            const long long row = cRow + wm * 32 + i * 16 + half * 8 + (lane >> 2);
            float rsum = 0.f;
            #pragma unroll
            for (int j = 0; j < 8; ++j) {
                const int col = cCol + wn * 64 + j * 8 + (lane & 3) * 2;
                float v0 = acc[i][j][half * 2 + 0];
                float v1 = acc[i][j][half * 2 + 1];
                if (EPI == 0 || EPI == 1 || EPI == 4) {
                    v0 += bias[col];
                    v1 += bias[col + 1];
                } else {
                    v0 = __expf(v0 * scale);
                    v1 = __expf(v1 * scale);
                    rsum += v0 + v1;
                }
                if (EPI == 0) {
                    *(float2*)(Cf + row * (long long)ldc + col) = make_float2(v0, v1);
                } else if (EPI == 1) {
                    __half2 h2, l2;
                    split2(v0, v1, h2, l2);
                    *(__half2*)(Ch + row * (long long)ldc + col) = h2;
                    *(__half2*)(Cl + row * (long long)ldc + col) = l2;
                } else {
                    *(__half2*)(Ch + row * (long long)ldc + col) = __floats2half2_rn(v0, v1);
                }
            }
            if (EPI == 2) {
                rsum += __shfl_xor_sync(0xffffffffu, rsum, 1);
                rsum += __shfl_xor_sync(0xffffffffu, rsum, 2);
                if ((lane & 3) == 0)
                    atomicAdd(partial + ((long long)z * 16 + bx) * 2048 + row, rsum);
            }
        }
    }
}

// ---------------------------------------------------------------------------
// Merged projections: grid (4, 64, 3). ALL 1-pass.
// z=0 Q -> hi/lo out, z=1 K -> single fp16 out, z=2 V -> written TRANSPOSED.
// ---------------------------------------------------------------------------
#define SV_STRIDE 130

__global__ void __launch_bounds__(256, 2)
gemm_proj(const hf* __restrict__ qh, const hf* __restrict__ kh, const hf* __restrict__ vh,
          const hf* __restrict__ WqTh, const hf* __restrict__ WkTh,
          const hf* __restrict__ WvTh,
          hf* __restrict__ Qeh, hf* __restrict__ Qel,
          hf* __restrict__ Kph,
          hf* __restrict__ VtH,
          const float* __restrict__ bqe, const float* __restrict__ bk,
          const float* __restrict__ bv)
{
    extern __shared__ char dsm_raw[];
    const uint32_t raw = smem_u32(dsm_raw);
    const uint32_t sbase = (raw + 1023) & ~1023u;
    hf* sv = (hf*)(dsm_raw + (sbase - raw));
    const int t = threadIdx.x;
    const int wid = t >> 5, lane = t & 31;
    const int wm = wid & 3, wn = wid >> 2;
    const int z = blockIdx.z;
    const int cRow = blockIdx.y * 128;
    const int cCol = blockIdx.x * 128;

    float acc[2][8][4];
    #pragma unroll
    for (int i = 0; i < 2; ++i)
        #pragma unroll
        for (int j = 0; j < 8; ++j)
            #pragma unroll
            for (int q = 0; q < 4; ++q) acc[i][j][q] = 0.f;

    if (z == 0) {
        gemm_core<0, false>(qh, nullptr, WqTh, nullptr, DM, DM, DM, cRow, cCol, sbase, t, acc);
        epilogue<1>(acc, nullptr, Qeh, Qel, bqe, nullptr, KVD_, cRow, cCol, 0, 0, t, 1.f);
    } else if (z == 1) {
        gemm_core<0, false>(kh, nullptr, WkTh, nullptr, DM, DM, DM, cRow, cCol, sbase, t, acc);
        epilogue<4>(acc, nullptr, Kph, nullptr, bk, nullptr, KVD_, cRow, cCol, 0, 0, t, 1.f);
    } else {
        gemm_core<0, false>(vh, nullptr, WvTh, nullptr, DM, DM, DM, cRow, cCol, sbase, t, acc);
        // V epilogue: bias + fp16 into smem [s_local][c_local], then write
        // transposed, coalesced along s, to Vt[b][c][s].
        #pragma unroll
        for (int i = 0; i < 2; ++i) {
            #pragma unroll
            for (int half = 0; half < 2; ++half) {
                const int lrow = wm * 32 + i * 16 + half * 8 + (lane >> 2);
                #pragma unroll
                for (int j = 0; j < 8; ++j) {
                    const int col = wn * 64 + j * 8 + (lane & 3) * 2;
                    float v0 = acc[i][j][half * 2 + 0] + bv[cCol + col];
                    float v1 = acc[i][j][half * 2 + 1] + bv[cCol + col + 1];
                    sv[lrow * SV_STRIDE + col]     = __float2half_rn(v0);
                    sv[lrow * SV_STRIDE + col + 1] = __float2half_rn(v1);
                }
            }
        }
        __syncthreads();
        {
            const int b  = cRow >> 11;
            const int s0 = cRow & 2047;
            hf* vt = VtH + (long long)b * ((long long)KVD_ * NQ)
                         + (long long)cCol * NQ + s0;
            #pragma unroll
            for (int i = 0; i < 32; ++i) {
                int id = t + i * 256;
                int cc = id >> 6;
                int sp = id & 63;
                __half2 hv = __halves2half2(sv[(2 * sp) * SV_STRIDE + cc],
                                            sv[(2 * sp + 1) * SV_STRIDE + cc]);
                *(__half2*)(vt + (long long)cc * NQ + 2 * sp) = hv;
            }
        }
    }
}

// ---------------------------------------------------------------------------
// Scores GEMM: E = exp(Q K^T / sqrt(128)), 2-pass (Qh+Ql)xKh, + partials
// ---------------------------------------------------------------------------
__global__ void __launch_bounds__(256, 2)
gemm_scores(const hf* __restrict__ Qeh, const hf* __restrict__ Qel,
            const hf* __restrict__ Kph,
            hf* __restrict__ Eh, float* __restrict__ partial, float scale)
{
    extern __shared__ char dsm_raw[];
    const uint32_t raw = smem_u32(dsm_raw);
    const uint32_t sbase = (raw + 1023) & ~1023u;
    const int t = threadIdx.x;

    const int z = blockIdx.z, zb = z >> 2, zh = z & 3;
    const long long seqS  = (long long)NQ * KVD_;
    const long long attnS = (long long)NQ * NQ;
    const long long qoff = zb * seqS + (long long)zh * HD_;
    const long long eoff = zb * (KVH_ * attnS) + zh * attnS;

    const int cRow = blockIdx.y * 128;
    const int cCol = blockIdx.x * 128;

    float acc[2][8][4];
    #pragma unroll
    for (int i = 0; i < 2; ++i)
        #pragma unroll
        for (int j = 0; j < 8; ++j)
            #pragma unroll
            for (int q = 0; q < 4; ++q) acc[i][j][q] = 0.f;

    gemm_core<3, false>(Qeh + qoff, Qel + qoff, Kph + qoff, nullptr,
                        HD_, KVD_, KVD_, cRow, cCol, sbase, t, acc);
    epilogue<2>(acc, nullptr, Eh + eoff, nullptr, nullptr, partial,
                NQ, cRow, cCol, z, blockIdx.x, t, scale);
}

// ---------------------------------------------------------------------------
// PV GEMM with fused P-write (P stores issued BEFORE MMA each chunk)
// ---------------------------------------------------------------------------
__global__ void __launch_bounds__(256, 2)
gemm_pv(const hf* __restrict__ Eh, const hf* __restrict__ VtH,
        hf* __restrict__ Xh, float* __restrict__ P,
        const float* __restrict__ invsum)
{
    extern __shared__ char dsm_raw[];
    const uint32_t raw = smem_u32(dsm_raw);
    const uint32_t sbase = (raw + 1023) & ~1023u;
    char* sm = dsm_raw + (sbase - raw);
    __shared__ float s_inv[128];

    const int t = threadIdx.x;
    const int wid = t >> 5, lane = t & 31;
    const int wm = wid & 3, wn = wid >> 2;

    const int z = blockIdx.z, zb = z >> 2, zh = z & 3;
    const long long attnS = (long long)NQ * NQ;
    const long long eoff = zb * (KVH_ * attnS) + zh * attnS;
    const hf* A = Eh + eoff;
    const hf* B = VtH + zb * ((long long)KVD_ * NQ) + zh * ((long long)HD_ * NQ);
    hf* Xp = Xh + zb * ((long long)NQ * KVD_) + zh * HD_;
    float* Pp = P + eoff;

    const int cRow = blockIdx.y * 128;
    if (t < 128) s_inv[t] = invsum[(long long)z * 2048 + cRow + t];

    float acc[2][8][4];
    #pragma unroll
    for (int i = 0; i < 2; ++i)
        #pragma unroll
        for (int j = 0; j < 8; ++j)
            #pragma unroll
            for (int q = 0; q < 4; ++q) acc[i][j][q] = 0.f;

    auto load_tile = [&](int c, int slot) {
        const uint32_t st = sbase + slot * STAGE_BYTES;
        const int k0 = c << 6;
        #pragma unroll
        for (int i = 0; i < 4; ++i) {
            int id = t + i * 256;
            int row = id >> 3, kc = id & 7;
            cp_async16(st + swz(row, kc * 16),
                       A + (long long)(cRow + row) * NQ + k0 + kc * 8);
        }
        #pragma unroll
        for (int i = 0; i < 4; ++i) {
            int id = t + i * 256;
            int row = id >> 3, kc = id & 7;
            cp_async16(st + 16384 + swz(row, kc * 16),
                       B + (long long)row * NQ + k0 + kc * 8);
        }
    };

    const uint32_t a_row0 = wm * 32 + (lane & 15);
    const uint32_t a_kb   = (lane >> 4) * 16;
    const uint32_t b_row0 = wn * 64 + (lane & 7) + ((lane >> 4) << 3);
    const uint32_t b_kb   = ((lane >> 3) & 1) * 16;

    const int KC = NQ >> 6;   // 32
    load_tile(0, 0); cp_commit();

    for (int c = 0; c < KC; ++c) {
        if (c + 1 < KC) { load_tile(c + 1, (c + 1) & 1); cp_commit(); cp_wait1(); }
        else            { cp_wait0(); }
        __syncthreads();

        const int slot = (c & 1);
        const uint32_t st = sbase + slot * STAGE_BYTES;
        char* stile = sm + slot * STAGE_BYTES;

        // fused P-write first (E tile resident in smem; STG drains under MMA)
        {
            const int k0 = c << 6;
            #pragma unroll
            for (int i = 0; i < 16; ++i) {
                int id2 = t + i * 256;
                int row = id2 >> 5;
                int c2  = id2 & 31;
                uint32_t off = row * 128u + ((c2 * 4u) ^ ((row & 7u) << 4));
                __half2 e = *(const __half2*)(stile + off);
                float f = s_inv[row];
                float2 v;
                v.x = __half2float(__low2half(e))  * f;
                v.y = __half2float(__high2half(e)) * f;
                *(float2*)(Pp + (long long)(cRow + row) * NQ + k0 + c2 * 2) = v;
            }
        }

        #pragma unroll
        for (int ks = 0; ks < 4; ++ks) {
            uint32_t afr[2][4], bfr[8][2];
            #pragma unroll
            for (int i = 0; i < 2; ++i)
                ldsm_x4(afr[i][0], afr[i][1], afr[i][2], afr[i][3],
                        st + swz(a_row0 + i * 16, ks * 32 + a_kb));
            #pragma unroll
            for (int j2 = 0; j2 < 4; ++j2)
                ldsm_x4(bfr[j2*2][0], bfr[j2*2][1], bfr[j2*2+1][0], bfr[j2*2+1][1],
                        st + 16384 + swz(b_row0 + j2 * 16, ks * 32 + b_kb));
            #pragma unroll
            for (int i = 0; i < 2; ++i)
                #pragma unroll
                for (int j = 0; j < 8; ++j)
                    mma_fp16(acc[i][j], afr[i], bfr[j]);
        }
        __syncthreads();
    }

    // epilogue: X = acc * invsum, single fp16
    #pragma unroll
    for (int i = 0; i < 2; ++i) {
        #pragma unroll
        for (int half = 0; half < 2; ++half) {
            const int lrow = wm * 32 + i * 16 + half * 8 + (lane >> 2);
            const float f = s_inv[lrow];
            const long long row = cRow + lrow;
            #pragma unroll
            for (int j = 0; j < 8; ++j) {
                const int col = wn * 64 + j * 8 + (lane & 3) * 2;
                *(__half2*)(Xp + row * (long long)KVD_ + col) =
                    __floats2half2_rn(acc[i][j][half*2] * f, acc[i][j][half*2+1] * f);
            }
        }
    }
}

// ---------------------------------------------------------------------------
// Out-projection GEMM: out = X @ WoT^T + bo (1-pass)
// ---------------------------------------------------------------------------
__global__ void __launch_bounds__(256, 2)
gemm_out(const hf* __restrict__ Xh, const hf* __restrict__ WoTh,
         float* __restrict__ out, const float* __restrict__ bo)
{
    extern __shared__ char dsm_raw[];
    const uint32_t raw = smem_u32(dsm_raw);
    const uint32_t sbase = (raw + 1023) & ~1023u;
    const int t = threadIdx.x;
    const int cRow = blockIdx.y * 128;
    const int cCol = blockIdx.x * 128;

    float acc[2][8][4];
    #pragma unroll
    for (int i = 0; i < 2; ++i)
        #pragma unroll
        for (int j = 0; j < 8; ++j)
            #pragma unroll
            for (int q = 0; q < 4; ++q) acc[i][j][q] = 0.f;

    gemm_core<0, false>(Xh, nullptr, WoTh, nullptr, KVD_, KVD_, KVD_, cRow, cCol, sbase, t, acc);
    epilogue<0>(acc, out, nullptr, nullptr, bo, nullptr, DM, cRow, cCol, 0, 0, t, 1.f);
}

// ---------------------------------------------------------------------------
// Merged prep A: inputs -> fp16 (y=0..2); y=3: bq fold + zero partials
// ---------------------------------------------------------------------------
__global__ void prep_inputs(const float* __restrict__ a0, const float* __restrict__ a1,
                            const float* __restrict__ a2, const float* __restrict__ bq,
                            hf* o0, hf* o1, hf* o2, float* __restrict__ partial,
                            long long n4) {
    if (blockIdx.y == 3) {
        long long id = (long long)blockIdx.x * 256 + threadIdx.x;
        if (id < KVD_) {
            int kvh = (int)(id >> 7), d = (int)(id & 127);
            float s = 0.f;
            #pragma unroll
            for (int g = 0; g < GRP_; ++g)
                s += bq[(kvh * GRP_ + g) * HD_ + d];
            g_bq_eff[id] = s;
        }
        if (id < 16LL * 16 * 2048) partial[id] = 0.f;
        return;
    }
    const float* in; hf* o;
    if (blockIdx.y == 0)      { in = a0; o = o0; }
    else if (blockIdx.y == 1) { in = a1; o = o1; }
    else                      { in = a2; o = o2; }
    long long i = (long long)blockIdx.x * 256 + threadIdx.x;
    if (i >= n4) return;
    float4 v = ((const float4*)in)[i];
    __half2* hp = (__half2*)o;
    hp[2*i]   = __floats2half2_rn(v.x, v.y);
    hp[2*i+1] = __floats2half2_rn(v.z, v.w);
}

// ---------------------------------------------------------------------------
// Merged prep B: weight transposes (single fp16 each). z=0 Wq (group-sum
// fold), z=1 Wk, z=2 Wv, z=3 Wo (block roles swapped). Grid (16, 64, 4).
// ---------------------------------------------------------------------------
__global__ void prep_weights(const float* __restrict__ Wq, const float* __restrict__ Wk,
                             const float* __restrict__ Wv, const float* __restrict__ Wo,
                             hf* h0, hf* h1, hf* h2, hf* h3) {
    __shared__ float tile[32][33];
    const int zz = blockIdx.z;
    hf* ohp;
    int R, C, x0, y0;
    if (zz < 3) {
        R = DM; C = KVD_;
        x0 = blockIdx.x * 32; y0 = blockIdx.y * 32;
        ohp = (zz == 0) ? h0 : (zz == 1) ? h1 : h2;
    } else {
        R = KVD_; C = DM;
        x0 = blockIdx.y * 32; y0 = blockIdx.x * 32;   // swapped roles
        ohp = h3;
    }
    int tx = threadIdx.x, ty = threadIdx.y;
    #pragma unroll
    for (int i = 0; i < 4; ++i) {
        int r = y0 + ty + i * 8;
        int c = x0 + tx;
        float v;
        if (zz == 0) {
            int kvh = c >> 7, d = c & 127;
            const float* wp = Wq + (long long)r * DM + (kvh * GRP_) * HD_ + d;
            v = wp[0] + wp[HD_] + wp[2*HD_] + wp[3*HD_];
        } else {
            const float* ip = (zz == 1) ? Wk : (zz == 2) ? Wv : Wo;
            v = ip[(long long)r * C + c];
        }
        tile[ty + i * 8][tx] = v;
    }
    __syncthreads();
    #pragma unroll
    for (int i = 0; i < 4; ++i) {
        int c = x0 + ty + i * 8;
        ohp[(long long)c * R + y0 + tx] = __float2half_rn(tile[tx][ty + i * 8]);
    }
}

// invsum[z*2048+row] = 1 / sum_x partial[z][x][row]
__global__ void rowsum_inv(const float* __restrict__ partial, float* __restrict__ invsum) {
    int idx = blockIdx.x * 256 + threadIdx.x;
    if (idx >= 16 * 2048) return;
    int zz = idx >> 11, row = idx & 2047;
    float s = 0.f;
    #pragma unroll
    for (int x = 0; x < 16; ++x)
        s += partial[((long long)zz * 16 + x) * 2048 + row];
    invsum[idx] = 1.f / s;
}

// ---------------------------------------------------------------------------
extern "C" void kernel_launch(void* const* d_in, const int* in_sizes, int n_in,
                              void* d_out, int out_size)
{
    const float* query = (const float*)d_in[0];
    const float* key   = (const float*)d_in[1];
    const float* value = (const float*)d_in[2];
    const float* Wq    = (const float*)d_in[3];
    const float* bq    = (const float*)d_in[4];
    const float* Wk    = (const float*)d_in[5];
    const float* bk    = (const float*)d_in[6];
    const float* Wv    = (const float*)d_in[7];
    const float* bv    = (const float*)d_in[8];
    const float* Wo    = (const float*)d_in[9];
    const float* bo    = (const float*)d_in[10];
    float* out = (float*)d_out;

    float *bq_eff, *attn_fb, *partial, *invsum;
    hf *qh,*kh,*vh;
    hf *WqTh,*WkTh,*WvTh,*WoTh;
    hf *Qeh,*Qel,*Kph,*Xh,*VtH,*Eh;
    cudaGetSymbolAddress((void**)&bq_eff, g_bq_eff);
    cudaGetSymbolAddress((void**)&attn_fb, g_attn_fb);
    cudaGetSymbolAddress((void**)&partial, g_partial);
    cudaGetSymbolAddress((void**)&invsum, g_invsum);
    cudaGetSymbolAddress((void**)&qh, g_qh);
    cudaGetSymbolAddress((void**)&kh, g_kh);
    cudaGetSymbolAddress((void**)&vh, g_vh);
    cudaGetSymbolAddress((void**)&WqTh, g_WqTh);
    cudaGetSymbolAddress((void**)&WkTh, g_WkTh);
    cudaGetSymbolAddress((void**)&WvTh, g_WvTh);
    cudaGetSymbolAddress((void**)&WoTh, g_WoTh);
    cudaGetSymbolAddress((void**)&Qeh, g_Qeh); cudaGetSymbolAddress((void**)&Qel, g_Qel);
    cudaGetSymbolAddress((void**)&Kph, g_Kph);
    cudaGetSymbolAddress((void**)&Xh,  g_Xh);
    cudaGetSymbolAddress((void**)&VtH, g_VtH);
    cudaGetSymbolAddress((void**)&Eh,  g_Eh);

    const long long XSZ = (long long)BQ * NQ * DM;
    const long long ASZ = (long long)BQ * KVH_ * NQ * NQ;
    float* attn = ((long long)out_size >= XSZ + ASZ) ? (out + XSZ) : attn_fb;

    const float inv_sqrt_hd = 0.08838834764831845f;
    cudaFuncSetAttribute(gemm_proj,   cudaFuncAttributeMaxDynamicSharedMemorySize, SMEM_DYN);
    cudaFuncSetAttribute(gemm_scores, cudaFuncAttributeMaxDynamicSharedMemorySize, SMEM_DYN);
    cudaFuncSetAttribute(gemm_pv,     cudaFuncAttributeMaxDynamicSharedMemorySize, SMEM_DYN);
    cudaFuncSetAttribute(gemm_out,    cudaFuncAttributeMaxDynamicSharedMemorySize, SMEM_DYN);

    // 1) inputs -> fp16; bq fold; zero partials
    {
        long long n4 = (long long)BQ * NQ * DM / 4;
        dim3 g((unsigned)((n4 + 255) / 256), 4);
        prep_inputs<<<g, 256>>>(query, key, value, bq, qh, kh, vh, partial, n4);
    }

    // 2) weight transposes (Wq fold, Wk, Wv, Wo — all single fp16)
    {
        dim3 blk(32, 8);
        prep_weights<<<dim3(16, 64, 4), blk>>>(Wq, Wk, Wv, Wo,
            WqTh, WkTh, WvTh, WoTh);
    }

    // 3) merged projections (all 1-pass), K single out, V written transposed
    gemm_proj<<<dim3(KVD_/128, (BQ*NQ)/128, 3), 256, SMEM_DYN>>>(
        qh, kh, vh, WqTh, WkTh, WvTh,
        Qeh, Qel, Kph, VtH, bq_eff, bk, bv);

    // 4) scores + exp + partial rowsums (2-pass: (Qh+Ql) x Kh)
    gemm_scores<<<dim3(NQ/128, NQ/128, BQ*KVH_), 256, SMEM_DYN>>>(
        Qeh, Qel, Kph, Eh, partial, inv_sqrt_hd);

    // 5) invsum
    rowsum_inv<<<(16 * 2048 + 255) / 256, 256>>>(partial, invsum);

    // 6) PV + fused P-write
    gemm_pv<<<dim3(1, NQ/128, BQ*KVH_), 256, SMEM_DYN>>>(Eh, VtH, Xh, attn, invsum);

    // 7) out = X @ Wo + bo
    gemm_out<<<dim3(DM/128, (BQ*NQ)/128), 256, SMEM_DYN>>>(Xh, WoTh, out, bo);
}

// round 17
// speedup vs baseline: 1.3626x; 1.3626x over previous
#include <cuda_runtime.h>
#include <cuda_fp16.h>
#include <cstdint>
#include <math.h>

typedef __half hf;

// Problem constants
#define BQ   4
#define NQ   2048
#define DM   2048
#define KVH_ 4
#define HD_  128
#define KVD_ 512
#define GRP_ 4

// ---------------------------------------------------------------------------
// Device scratch
// ---------------------------------------------------------------------------
__device__ float g_bq_eff[KVD_];

__device__ hf g_qh[(size_t)BQ * NQ * DM];
__device__ hf g_kh[(size_t)BQ * NQ * DM];
__device__ hf g_vh[(size_t)BQ * NQ * DM];

__device__ hf g_WqTh[DM * KVD_];
__device__ hf g_WkTh[DM * KVD_];
__device__ hf g_WvTh[DM * KVD_];
__device__ hf g_WoTh[DM * KVD_];

__device__ hf g_VtH[(size_t)BQ * KVD_ * NQ];

__device__ hf g_Qeh[(size_t)BQ * NQ * KVD_], g_Qel[(size_t)BQ * NQ * KVD_];
__device__ hf g_Kph[(size_t)BQ * NQ * KVD_], g_Kpl[(size_t)BQ * NQ * KVD_];
__device__ hf g_Xh [(size_t)BQ * NQ * KVD_];

__device__ hf g_Eh[(size_t)BQ * KVH_ * NQ * NQ];
__device__ float g_partial[16 * 16 * 2048];   // [z][xtile][row]
__device__ float g_attn_fb[(size_t)BQ * KVH_ * NQ * NQ];

// ---------------------------------------------------------------------------
// Helpers
// ---------------------------------------------------------------------------
__device__ __forceinline__ uint32_t smem_u32(const void* p) {
    uint32_t a;
    asm("{ .reg .u64 t; cvta.to.shared.u64 t, %1; cvt.u32.u64 %0, t; }" : "=r"(a) : "l"(p));
    return a;
}
__device__ __forceinline__ uint32_t swz(uint32_t row, uint32_t kb) {
    return row * 128u + (kb ^ ((row & 7u) << 4));
}
__device__ __forceinline__ void cp_async16(uint32_t dst, const void* src) {
    asm volatile("cp.async.cg.shared.global [%0], [%1], 16;" :: "r"(dst), "l"(src));
}
__device__ __forceinline__ void cp_commit() {
    asm volatile("cp.async.commit_group;" ::: "memory");
}
__device__ __forceinline__ void cp_wait1() {
    asm volatile("cp.async.wait_group 1;" ::: "memory");
}
__device__ __forceinline__ void cp_wait0() {
    asm volatile("cp.async.wait_group 0;" ::: "memory");
}
__device__ __forceinline__ void ldsm_x4(uint32_t& r0, uint32_t& r1, uint32_t& r2,
                                        uint32_t& r3, uint32_t addr) {
    asm volatile("ldmatrix.sync.aligned.m8n8.x4.shared.b16 {%0,%1,%2,%3}, [%4];"
        : "=r"(r0), "=r"(r1), "=r"(r2), "=r"(r3) : "r"(addr));
}
__device__ __forceinline__ void mma_fp16(float* c, const uint32_t* a, const uint32_t* b) {
    asm volatile(
        "mma.sync.aligned.m16n8k16.row.col.f32.f16.f16.f32 "
        "{%0,%1,%2,%3}, {%4,%5,%6,%7}, {%8,%9}, {%0,%1,%2,%3};"
        : "+f"(c[0]), "+f"(c[1]), "+f"(c[2]), "+f"(c[3])
        : "r"(a[0]), "r"(a[1]), "r"(a[2]), "r"(a[3]), "r"(b[0]), "r"(b[1]));
}
__device__ __forceinline__ void split2(float v0, float v1, __half2& h, __half2& l) {
    hf h0 = __float2half_rn(v0), h1 = __float2half_rn(v1);
    h = __halves2half2(h0, h1);
    l = __halves2half2(__float2half_rn(v0 - __half2float(h0)),
                       __float2half_rn(v1 - __half2float(h1)));
}

#define STAGE_BYTES 49152
#define SMEM_DYN (2 * STAGE_BYTES + 1024)

// ---------------------------------------------------------------------------
// GEMM mainloop core (round-10 proven form). MODE: 0 = 1-pass {A,Bh};
// 2 = 3-pass (phase A {Ah,Al,Bh}; phase B {Ah,Bl});
// REUSEA valid when KC<=2. Ends with trailing __syncthreads().
// ---------------------------------------------------------------------------
template <int MODE, bool REUSEA>
__device__ __forceinline__ void gemm_core(
    const hf* __restrict__ Ah, const hf* __restrict__ Al,
    const hf* __restrict__ Bh, const hf* __restrict__ Bl,
    int K, int lda, int ldb, int cRow, int cCol,
    uint32_t sbase, int t, float acc[2][8][4])
{
    const int wid = t >> 5;
    const int lane = t & 31;
    const int wm = wid & 3;
    const int wn = wid >> 2;

    const int KC = K >> 6;
    const int NC = (MODE == 2) ? 2 * KC : KC;

    auto loadOp = [&](uint32_t dst, const hf* P, int ld, int base, int k0) {
        #pragma unroll
        for (int i = 0; i < 4; ++i) {
            int id = t + i * 256;
            int row = id >> 3, kc = id & 7;
            cp_async16(dst + swz(row, kc * 16),
                       P + (long long)(base + row) * ld + k0 + kc * 8);
        }
    };

    auto load_tile = [&](int c, int slot) {
        const uint32_t st = sbase + slot * STAGE_BYTES;
        if (MODE == 2) {
            const bool phA = (c < KC);
            const int k0 = (phA ? c : c - KC) << 6;
            if (phA || !REUSEA) loadOp(st, Ah, lda, cRow, k0);
            if (phA) loadOp(st + 16384, Al, lda, cRow, k0);
            loadOp(st + 32768, phA ? Bh : Bl, ldb, cCol, k0);
        } else {
            const int k0 = c << 6;
            loadOp(st, Ah, lda, cRow, k0);
            loadOp(st + 16384, Bh, ldb, cCol, k0);
        }
    };

    const uint32_t a_row0 = wm * 32 + (lane & 15);
    const uint32_t a_kb   = (lane >> 4) * 16;
    const uint32_t b_row0 = wn * 64 + (lane & 7) + ((lane >> 4) << 3);
    const uint32_t b_kb   = ((lane >> 3) & 1) * 16;

    load_tile(0, 0); cp_commit();

    for (int c = 0; c < NC; ++c) {
        if (c + 1 < NC) { load_tile(c + 1, (c + 1) & 1); cp_commit(); cp_wait1(); }
        else            { cp_wait0(); }
        __syncthreads();

        const uint32_t st = sbase + (c & 1) * STAGE_BYTES;

        #pragma unroll
        for (int ks = 0; ks < 4; ++ks) {
            uint32_t afr[2][4];
            #pragma unroll
            for (int i = 0; i < 2; ++i)
                ldsm_x4(afr[i][0], afr[i][1], afr[i][2], afr[i][3],
                        st + swz(a_row0 + i * 16, ks * 32 + a_kb));

            if (MODE == 2) {
                uint32_t bfr[8][2];
                #pragma unroll
                for (int j2 = 0; j2 < 4; ++j2)
                    ldsm_x4(bfr[j2*2][0], bfr[j2*2][1], bfr[j2*2+1][0], bfr[j2*2+1][1],
                            st + 32768 + swz(b_row0 + j2 * 16, ks * 32 + b_kb));
                #pragma unroll
                for (int i = 0; i < 2; ++i)
                    #pragma unroll
                    for (int j = 0; j < 8; ++j)
                        mma_fp16(acc[i][j], afr[i], bfr[j]);
                if (c < KC) {
                    uint32_t afr2[2][4];
                    #pragma unroll
                    for (int i = 0; i < 2; ++i)
                        ldsm_x4(afr2[i][0], afr2[i][1], afr2[i][2], afr2[i][3],
                                st + 16384 + swz(a_row0 + i * 16, ks * 32 + a_kb));
                    #pragma unroll
                    for (int i = 0; i < 2; ++i)
                        #pragma unroll
                        for (int j = 0; j < 8; ++j)
                            mma_fp16(acc[i][j], afr2[i], bfr[j]);
                }
            } else {
                uint32_t bfr[8][2];
                #pragma unroll
                for (int j2 = 0; j2 < 4; ++j2)
                    ldsm_x4(bfr[j2*2][0], bfr[j2*2][1], bfr[j2*2+1][0], bfr[j2*2+1][1],
                            st + 16384 + swz(b_row0 + j2 * 16, ks * 32 + b_kb));
                #pragma unroll
                for (int i = 0; i < 2; ++i)
                    #pragma unroll
                    for (int j = 0; j < 8; ++j)
                        mma_fp16(acc[i][j], afr[i], bfr[j]);
            }
        }
        __syncthreads();
    }
}

// ---------------------------------------------------------------------------
// Epilogue. EPI: 0 fp32+bias | 1 hi/lo fp16+bias | 2 exp->fp16 + partials
// ---------------------------------------------------------------------------
template <int EPI>
__device__ __forceinline__ void epilogue(
    float acc[2][8][4], float* Cf, hf* Ch, hf* Cl,
    const float* bias, float* partial,
    int ldc, int cRow, int cCol, int z, int bx, int t, float scale)
{
    const int wid = t >> 5, lane = t & 31;
    const int wm = wid & 3, wn = wid >> 2;
    #pragma unroll
    for (int i = 0; i < 2; ++i) {
        #pragma unroll
        for (int half = 0; half < 2; ++half) {
            const long long row = cRow + wm * 32 + i * 16 + half * 8 + (lane >> 2);
            float rsum = 0.f;
            #pragma unroll
            for (int j = 0; j < 8; ++j) {
                const int col = cCol + wn * 64 + j * 8 + (lane & 3) * 2;
                float v0 = acc[i][j][half * 2 + 0];
                float v1 = acc[i][j][half * 2 + 1];
                if (EPI == 0 || EPI == 1) {
                    v0 += bias[col];
                    v1 += bias[col + 1];
                } else {
                    v0 = __expf(v0 * scale);
                    v1 = __expf(v1 * scale);
                    rsum += v0 + v1;
                }
                if (EPI == 0) {
                    *(float2*)(Cf + row * (long long)ldc + col) = make_float2(v0, v1);
                } else if (EPI == 1) {
                    __half2 h2, l2;
                    split2(v0, v1, h2, l2);
                    *(__half2*)(Ch + row * (long long)ldc + col) = h2;
                    *(__half2*)(Cl + row * (long long)ldc + col) = l2;
                } else {
                    *(__half2*)(Ch + row * (long long)ldc + col) = __floats2half2_rn(v0, v1);
                }
            }
            if (EPI == 2) {
                rsum += __shfl_xor_sync(0xffffffffu, rsum, 1);
                rsum += __shfl_xor_sync(0xffffffffu, rsum, 2);
                if ((lane & 3) == 0)
                    atomicAdd(partial + ((long long)z * 16 + bx) * 2048 + row, rsum);
            }
        }
    }
}

// ---------------------------------------------------------------------------
// Merged projections: grid (4, 64, 3). ALL 1-pass.
// z=0 Q -> hi/lo out, z=1 K -> hi/lo out, z=2 V -> written TRANSPOSED.
// ---------------------------------------------------------------------------
#define SV_STRIDE 130

__global__ void __launch_bounds__(256, 2)
gemm_proj(const hf* __restrict__ qh, const hf* __restrict__ kh, const hf* __restrict__ vh,
          const hf* __restrict__ WqTh, const hf* __restrict__ WkTh,
          const hf* __restrict__ WvTh,
          hf* __restrict__ Qeh, hf* __restrict__ Qel,
          hf* __restrict__ Kph, hf* __restrict__ Kpl,
          hf* __restrict__ VtH,
          const float* __restrict__ bqe, const float* __restrict__ bk,
          const float* __restrict__ bv)
{
    extern __shared__ char dsm_raw[];
    const uint32_t raw = smem_u32(dsm_raw);
    const uint32_t sbase = (raw + 1023) & ~1023u;
    hf* sv = (hf*)(dsm_raw + (sbase - raw));
    const int t = threadIdx.x;
    const int wid = t >> 5, lane = t & 31;
    const int wm = wid & 3, wn = wid >> 2;
    const int z = blockIdx.z;
    const int cRow = blockIdx.y * 128;
    const int cCol = blockIdx.x * 128;

    float acc[2][8][4];
    #pragma unroll
    for (int i = 0; i < 2; ++i)
        #pragma unroll
        for (int j = 0; j < 8; ++j)
            #pragma unroll
            for (int q = 0; q < 4; ++q) acc[i][j][q] = 0.f;

    if (z == 0) {
        gemm_core<0, false>(qh, nullptr, WqTh, nullptr, DM, DM, DM, cRow, cCol, sbase, t, acc);
        epilogue<1>(acc, nullptr, Qeh, Qel, bqe, nullptr, KVD_, cRow, cCol, 0, 0, t, 1.f);
    } else if (z == 1) {
        gemm_core<0, false>(kh, nullptr, WkTh, nullptr, DM, DM, DM, cRow, cCol, sbase, t, acc);
        epilogue<1>(acc, nullptr, Kph, Kpl, bk, nullptr, KVD_, cRow, cCol, 0, 0, t, 1.f);
    } else {
        gemm_core<0, false>(vh, nullptr, WvTh, nullptr, DM, DM, DM, cRow, cCol, sbase, t, acc);
        // V epilogue: bias + fp16 into smem [s_local][c_local], then write
        // transposed, coalesced along s, to Vt[b][c][s].
        #pragma unroll
        for (int i = 0; i < 2; ++i) {
            #pragma unroll
            for (int half = 0; half < 2; ++half) {
                const int lrow = wm * 32 + i * 16 + half * 8 + (lane >> 2);
                #pragma unroll
                for (int j = 0; j < 8; ++j) {
                    const int col = wn * 64 + j * 8 + (lane & 3) * 2;
                    float v0 = acc[i][j][half * 2 + 0] + bv[cCol + col];
                    float v1 = acc[i][j][half * 2 + 1] + bv[cCol + col + 1];
                    sv[lrow * SV_STRIDE + col]     = __float2half_rn(v0);
                    sv[lrow * SV_STRIDE + col + 1] = __float2half_rn(v1);
                }
            }
        }
        __syncthreads();
        {
            const int b  = cRow >> 11;
            const int s0 = cRow & 2047;
            hf* vt = VtH + (long long)b * ((long long)KVD_ * NQ)
                         + (long long)cCol * NQ + s0;
            #pragma unroll
            for (int i = 0; i < 32; ++i) {
                int id = t + i * 256;
                int cc = id >> 6;
                int sp = id & 63;
                __half2 hv = __halves2half2(sv[(2 * sp) * SV_STRIDE + cc],
                                            sv[(2 * sp + 1) * SV_STRIDE + cc]);
                *(__half2*)(vt + (long long)cc * NQ + 2 * sp) = hv;
            }
        }
    }
}

// ---------------------------------------------------------------------------
// Scores GEMM: E = exp(Q K^T / sqrt(128)), 3-pass, + partial rowsums
// ---------------------------------------------------------------------------
__global__ void __launch_bounds__(256, 2)
gemm_scores(const hf* __restrict__ Qeh, const hf* __restrict__ Qel,
            const hf* __restrict__ Kph, const hf* __restrict__ Kpl,
            hf* __restrict__ Eh, float* __restrict__ partial, float scale)
{
    extern __shared__ char dsm_raw[];
    const uint32_t raw = smem_u32(dsm_raw);
    const uint32_t sbase = (raw + 1023) & ~1023u;
    const int t = threadIdx.x;

    const int z = blockIdx.z, zb = z >> 2, zh = z & 3;
    const long long seqS  = (long long)NQ * KVD_;
    const long long attnS = (long long)NQ * NQ;
    const long long qoff = zb * seqS + (long long)zh * HD_;
    const long long eoff = zb * (KVH_ * attnS) + zh * attnS;

    const int cRow = blockIdx.y * 128;
    const int cCol = blockIdx.x * 128;

    float acc[2][8][4];
    #pragma unroll
    for (int i = 0; i < 2; ++i)
        #pragma unroll
        for (int j = 0; j < 8; ++j)
            #pragma unroll
            for (int q = 0; q < 4; ++q) acc[i][j][q] = 0.f;

    gemm_core<2, true>(Qeh + qoff, Qel + qoff, Kph + qoff, Kpl + qoff,
                       HD_, KVD_, KVD_, cRow, cCol, sbase, t, acc);
    epilogue<2>(acc, nullptr, Eh + eoff, nullptr, nullptr, partial,
                NQ, cRow, cCol, z, blockIdx.x, t, scale);
}

// ---------------------------------------------------------------------------
// PV GEMM with fused P-write; computes s_inv from partial rowsums directly
// (same x=0..15 summation order as the old rowsum_inv kernel -> bit-identical)
// ---------------------------------------------------------------------------
__global__ void __launch_bounds__(256, 2)
gemm_pv(const hf* __restrict__ Eh, const hf* __restrict__ VtH,
        hf* __restrict__ Xh, float* __restrict__ P,
        const float* __restrict__ partial)
{
    extern __shared__ char dsm_raw[];
    const uint32_t raw = smem_u32(dsm_raw);
    const uint32_t sbase = (raw + 1023) & ~1023u;
    char* sm = dsm_raw + (sbase - raw);
    __shared__ float s_inv[128];

    const int t = threadIdx.x;
    const int wid = t >> 5, lane = t & 31;
    const int wm = wid & 3, wn = wid >> 2;

    const int z = blockIdx.z, zb = z >> 2, zh = z & 3;
    const long long attnS = (long long)NQ * NQ;
    const long long eoff = zb * (KVH_ * attnS) + zh * attnS;
    const hf* A = Eh + eoff;
    const hf* B = VtH + zb * ((long long)KVD_ * NQ) + zh * ((long long)HD_ * NQ);
    hf* Xp = Xh + zb * ((long long)NQ * KVD_) + zh * HD_;
    float* Pp = P + eoff;

    const int cRow = blockIdx.y * 128;

    float acc[2][8][4];
    #pragma unroll
    for (int i = 0; i < 2; ++i)
        #pragma unroll
        for (int j = 0; j < 8; ++j)
            #pragma unroll
            for (int q = 0; q < 4; ++q) acc[i][j][q] = 0.f;

    auto load_tile = [&](int c, int slot) {
        const uint32_t st = sbase + slot * STAGE_BYTES;
        const int k0 = c << 6;
        #pragma unroll
        for (int i = 0; i < 4; ++i) {
            int id = t + i * 256;
            int row = id >> 3, kc = id & 7;
            cp_async16(st + swz(row, kc * 16),
                       A + (long long)(cRow + row) * NQ + k0 + kc * 8);
        }
        #pragma unroll
        for (int i = 0; i < 4; ++i) {
            int id = t + i * 256;
            int row = id >> 3, kc = id & 7;
            cp_async16(st + 16384 + swz(row, kc * 16),
                       B + (long long)row * NQ + k0 + kc * 8);
        }
    };

    const uint32_t a_row0 = wm * 32 + (lane & 15);
    const uint32_t a_kb   = (lane >> 4) * 16;
    const uint32_t b_row0 = wn * 64 + (lane & 7) + ((lane >> 4) << 3);
    const uint32_t b_kb   = ((lane >> 3) & 1) * 16;

    const int KC = NQ >> 6;   // 32
    load_tile(0, 0); cp_commit();

    // fused invsum: sum 16 x-tile partials per row (same order as rowsum_inv)
    if (t < 128) {
        const float* pp = partial + (long long)z * 16 * 2048 + (cRow + t);
        float s = 0.f;
        #pragma unroll
        for (int x = 0; x < 16; ++x)
            s += pp[(long long)x * 2048];
        s_inv[t] = 1.f / s;
    }

    for (int c = 0; c < KC; ++c) {
        if (c + 1 < KC) { load_tile(c + 1, (c + 1) & 1); cp_commit(); cp_wait1(); }
        else            { cp_wait0(); }
        __syncthreads();

        const int slot = (c & 1);
        const uint32_t st = sbase + slot * STAGE_BYTES;
        char* stile = sm + slot * STAGE_BYTES;

        // fused P-write first (E tile resident in smem; STG drains under MMA)
        {
            const int k0 = c << 6;
            #pragma unroll
            for (int i = 0; i < 16; ++i) {
                int id2 = t + i * 256;
                int row = id2 >> 5;
                int c2  = id2 & 31;
                uint32_t off = row * 128u + ((c2 * 4u) ^ ((row & 7u) << 4));
                __half2 e = *(const __half2*)(stile + off);
                float f = s_inv[row];
                float2 v;
                v.x = __half2float(__low2half(e))  * f;
                v.y = __half2float(__high2half(e)) * f;
                *(float2*)(Pp + (long long)(cRow + row) * NQ + k0 + c2 * 2) = v;
            }
        }

        #pragma unroll
        for (int ks = 0; ks < 4; ++ks) {
            uint32_t afr[2][4], bfr[8][2];
            #pragma unroll
            for (int i = 0; i < 2; ++i)
                ldsm_x4(afr[i][0], afr[i][1], afr[i][2], afr[i][3],
                        st + swz(a_row0 + i * 16, ks * 32 + a_kb));
            #pragma unroll
            for (int j2 = 0; j2 < 4; ++j2)
                ldsm_x4(bfr[j2*2][0], bfr[j2*2][1], bfr[j2*2+1][0], bfr[j2*2+1][1],
                        st + 16384 + swz(b_row0 + j2 * 16, ks * 32 + b_kb));
            #pragma unroll
            for (int i = 0; i < 2; ++i)
                #pragma unroll
                for (int j = 0; j < 8; ++j)
                    mma_fp16(acc[i][j], afr[i], bfr[j]);
        }
        __syncthreads();
    }

    // epilogue: X = acc * invsum, single fp16
    #pragma unroll
    for (int i = 0; i < 2; ++i) {
        #pragma unroll
        for (int half = 0; half < 2; ++half) {
            const int lrow = wm * 32 + i * 16 + half * 8 + (lane >> 2);
            const float f = s_inv[lrow];
            const long long row = cRow + lrow;
            #pragma unroll
            for (int j = 0; j < 8; ++j) {
                const int col = wn * 64 + j * 8 + (lane & 3) * 2;
                *(__half2*)(Xp + row * (long long)KVD_ + col) =
                    __floats2half2_rn(acc[i][j][half*2] * f, acc[i][j][half*2+1] * f);
            }
        }
    }
}

// ---------------------------------------------------------------------------
// Out-projection GEMM: out = X @ WoT^T + bo (1-pass)
// ---------------------------------------------------------------------------
__global__ void __launch_bounds__(256, 2)
gemm_out(const hf* __restrict__ Xh, const hf* __restrict__ WoTh,
         float* __restrict__ out, const float* __restrict__ bo)
{
    extern __shared__ char dsm_raw[];
    const uint32_t raw = smem_u32(dsm_raw);
    const uint32_t sbase = (raw + 1023) & ~1023u;
    const int t = threadIdx.x;
    const int cRow = blockIdx.y * 128;
    const int cCol = blockIdx.x * 128;

    float acc[2][8][4];
    #pragma unroll
    for (int i = 0; i < 2; ++i)
        #pragma unroll
        for (int j = 0; j < 8; ++j)
            #pragma unroll
            for (int q = 0; q < 4; ++q) acc[i][j][q] = 0.f;

    gemm_core<0, false>(Xh, nullptr, WoTh, nullptr, KVD_, KVD_, KVD_, cRow, cCol, sbase, t, acc);
    epilogue<0>(acc, out, nullptr, nullptr, bo, nullptr, DM, cRow, cCol, 0, 0, t, 1.f);
}

// ---------------------------------------------------------------------------
// Merged prep A: inputs -> fp16 (y=0..2); y=3: bq fold + zero partials
// ---------------------------------------------------------------------------
__global__ void prep_inputs(const float* __restrict__ a0, const float* __restrict__ a1,
                            const float* __restrict__ a2, const float* __restrict__ bq,
                            hf* o0, hf* o1, hf* o2, float* __restrict__ partial,
                            long long n4) {
    if (blockIdx.y == 3) {
        long long id = (long long)blockIdx.x * 256 + threadIdx.x;
        if (id < KVD_) {
            int kvh = (int)(id >> 7), d = (int)(id & 127);
            float s = 0.f;
            #pragma unroll
            for (int g = 0; g < GRP_; ++g)
                s += bq[(kvh * GRP_ + g) * HD_ + d];
            g_bq_eff[id] = s;
        }
        if (id < 16LL * 16 * 2048) partial[id] = 0.f;
        return;
    }
    const float* in; hf* o;
    if (blockIdx.y == 0)      { in = a0; o = o0; }
    else if (blockIdx.y == 1) { in = a1; o = o1; }
    else                      { in = a2; o = o2; }
    long long i = (long long)blockIdx.x * 256 + threadIdx.x;
    if (i >= n4) return;
    float4 v = ((const float4*)in)[i];
    __half2* hp = (__half2*)o;
    hp[2*i]   = __floats2half2_rn(v.x, v.y);
    hp[2*i+1] = __floats2half2_rn(v.z, v.w);
}

// ---------------------------------------------------------------------------
// Merged prep B: weight transposes (single fp16 each). z=0 Wq (group-sum
// fold), z=1 Wk, z=2 Wv, z=3 Wo (block roles swapped). Grid (16, 64, 4).
// ---------------------------------------------------------------------------
__global__ void prep_weights(const float* __restrict__ Wq, const float* __restrict__ Wk,
                             const float* __restrict__ Wv, const float* __restrict__ Wo,
                             hf* h0, hf* h1, hf* h2, hf* h3) {
    __shared__ float tile[32][33];
    const int zz = blockIdx.z;
    hf* ohp;
    int R, C, x0, y0;
    if (zz < 3) {
        R = DM; C = KVD_;
        x0 = blockIdx.x * 32; y0 = blockIdx.y * 32;
        ohp = (zz == 0) ? h0 : (zz == 1) ? h1 : h2;
    } else {
        R = KVD_; C = DM;
        x0 = blockIdx.y * 32; y0 = blockIdx.x * 32;   // swapped roles
        ohp = h3;
    }
    int tx = threadIdx.x, ty = threadIdx.y;
    #pragma unroll
    for (int i = 0; i < 4; ++i) {
        int r = y0 + ty + i * 8;
        int c = x0 + tx;
        float v;
        if (zz == 0) {
            int kvh = c >> 7, d = c & 127;
            const float* wp = Wq + (long long)r * DM + (kvh * GRP_) * HD_ + d;
            v = wp[0] + wp[HD_] + wp[2*HD_] + wp[3*HD_];
        } else {
            const float* ip = (zz == 1) ? Wk : (zz == 2) ? Wv : Wo;
            v = ip[(long long)r * C + c];
        }
        tile[ty + i * 8][tx] = v;
    }
    __syncthreads();
    #pragma unroll
    for (int i = 0; i < 4; ++i) {
        int c = x0 + ty + i * 8;
        ohp[(long long)c * R + y0 + tx] = __float2half_rn(tile[tx][ty + i * 8]);
    }
}

// ---------------------------------------------------------------------------
extern "C" void kernel_launch(void* const* d_in, const int* in_sizes, int n_in,
                              void* d_out, int out_size)
{
    const float* query = (const float*)d_in[0];
    const float* key   = (const float*)d_in[1];
    const float* value = (const float*)d_in[2];
    const float* Wq    = (const float*)d_in[3];
    const float* bq    = (const float*)d_in[4];
    const float* Wk    = (const float*)d_in[5];
    const float* bk    = (const float*)d_in[6];
    const float* Wv    = (const float*)d_in[7];
    const float* bv    = (const float*)d_in[8];
    const float* Wo    = (const float*)d_in[9];
    const float* bo    = (const float*)d_in[10];
    float* out = (float*)d_out;

    float *bq_eff, *attn_fb, *partial;
    hf *qh,*kh,*vh;
    hf *WqTh,*WkTh,*WvTh,*WoTh;
    hf *Qeh,*Qel,*Kph,*Kpl,*Xh,*VtH,*Eh;
    cudaGetSymbolAddress((void**)&bq_eff, g_bq_eff);
    cudaGetSymbolAddress((void**)&attn_fb, g_attn_fb);
    cudaGetSymbolAddress((void**)&partial, g_partial);
    cudaGetSymbolAddress((void**)&qh, g_qh);
    cudaGetSymbolAddress((void**)&kh, g_kh);
    cudaGetSymbolAddress((void**)&vh, g_vh);
    cudaGetSymbolAddress((void**)&WqTh, g_WqTh);
    cudaGetSymbolAddress((void**)&WkTh, g_WkTh);
    cudaGetSymbolAddress((void**)&WvTh, g_WvTh);
    cudaGetSymbolAddress((void**)&WoTh, g_WoTh);
    cudaGetSymbolAddress((void**)&Qeh, g_Qeh); cudaGetSymbolAddress((void**)&Qel, g_Qel);
    cudaGetSymbolAddress((void**)&Kph, g_Kph); cudaGetSymbolAddress((void**)&Kpl, g_Kpl);
    cudaGetSymbolAddress((void**)&Xh,  g_Xh);
    cudaGetSymbolAddress((void**)&VtH, g_VtH);
    cudaGetSymbolAddress((void**)&Eh,  g_Eh);

    const long long XSZ = (long long)BQ * NQ * DM;
    const long long ASZ = (long long)BQ * KVH_ * NQ * NQ;
    float* attn = ((long long)out_size >= XSZ + ASZ) ? (out + XSZ) : attn_fb;

    const float inv_sqrt_hd = 0.08838834764831845f;
    cudaFuncSetAttribute(gemm_proj,   cudaFuncAttributeMaxDynamicSharedMemorySize, SMEM_DYN);
    cudaFuncSetAttribute(gemm_scores, cudaFuncAttributeMaxDynamicSharedMemorySize, SMEM_DYN);
    cudaFuncSetAttribute(gemm_pv,     cudaFuncAttributeMaxDynamicSharedMemorySize, SMEM_DYN);
    cudaFuncSetAttribute(gemm_out,    cudaFuncAttributeMaxDynamicSharedMemorySize, SMEM_DYN);

    // 1) inputs -> fp16; bq fold; zero partials
    {
        long long n4 = (long long)BQ * NQ * DM / 4;
        dim3 g((unsigned)((n4 + 255) / 256), 4);
        prep_inputs<<<g, 256>>>(query, key, value, bq, qh, kh, vh, partial, n4);
    }

    // 2) weight transposes (Wq fold, Wk, Wv, Wo — all single fp16)
    {
        dim3 blk(32, 8);
        prep_weights<<<dim3(16, 64, 4), blk>>>(Wq, Wk, Wv, Wo,
            WqTh, WkTh, WvTh, WoTh);
    }

    // 3) merged projections (all 1-pass), V written transposed (grid 768)
    gemm_proj<<<dim3(KVD_/128, (BQ*NQ)/128, 3), 256, SMEM_DYN>>>(
        qh, kh, vh, WqTh, WkTh, WvTh,
        Qeh, Qel, Kph, Kpl, VtH, bq_eff, bk, bv);

    // 4) scores + exp + partial rowsums (3-pass on hi/lo Qe/Kp)
    gemm_scores<<<dim3(NQ/128, NQ/128, BQ*KVH_), 256, SMEM_DYN>>>(
        Qeh, Qel, Kph, Kpl, Eh, partial, inv_sqrt_hd);

    // 5) PV + fused P-write + fused invsum
    gemm_pv<<<dim3(1, NQ/128, BQ*KVH_), 256, SMEM_DYN>>>(Eh, VtH, Xh, attn, partial);

    // 6) out = X @ Wo + bo
    gemm_out<<<dim3(DM/128, (BQ*NQ)/128), 256, SMEM_DYN>>>(Xh, WoTh, out, bo);
}